// round 1
// baseline (speedup 1.0000x reference)
#include <cuda_runtime.h>
#include <cuda_bf16.h>
#include <stdint.h>

// Problem constants (fixed for this dataset instance)
#define NTOK 4096
#define NEDGE 131072
#define TNUM 8
#define RNUM 16
#define HNUM 8
#define BNUM 21
#define SEEDS 128

// ---------------------------------------------------------------------------
// Bucketize: matches the JAX reference in fp32.
//   signed_log = sign(dt) * log1p(|dt| + 1e-6)
//   norm = (clip(signed_log, -5, 5) + 5) / (10 + 1e-9)   (1e-9 vanishes in fp32)
//   idx = clip(floor(norm * (B-1)), 0, B-1)
// ---------------------------------------------------------------------------
__device__ __forceinline__ int bucketize(float dt) {
    float s  = (dt > 0.0f) ? 1.0f : ((dt < 0.0f) ? -1.0f : 0.0f);
    float sl = s * log1pf(fabsf(dt) + 1e-6f);
    float c  = fminf(fmaxf(sl, -5.0f), 5.0f);
    float norm = (c + 5.0f) / (10.0f + 1e-9f);
    int idx = (int)floorf(norm * (float)(BNUM - 1));
    idx = idx < 0 ? 0 : idx;
    idx = idx > (BNUM - 1) ? (BNUM - 1) : idx;
    return idx;
}

// ---------------------------------------------------------------------------
// Fill kernel: one block per (i, h) row. Writes out[h, i, 0..N) coalesced.
//   out[h,i,j] = typepair_bias[tt[i], tt[j], h]  (+ temp_bias[bucket, h] if i<SEEDS)
// Per-block state: 8-entry type LUT + 21-entry temp LUT in smem.
// ---------------------------------------------------------------------------
__global__ __launch_bounds__(256) void fill_kernel(
    const int*   __restrict__ token_type,
    const float* __restrict__ time_vec,
    const float* __restrict__ typepair_bias,  // (T, T, H)
    const float* __restrict__ temp_bias,      // (B, H)
    float*       __restrict__ out)            // (H, N, N)
{
    const int i = blockIdx.x;   // row index 0..N-1
    const int h = blockIdx.y;   // head 0..7
    const int tid = threadIdx.x;

    __shared__ float val8[TNUM];
    __shared__ float tb[BNUM];

    const int tt_i = token_type[i];
    if (tid < TNUM)  val8[tid] = typepair_bias[(tt_i * TNUM + tid) * HNUM + h];
    if (tid < BNUM)  tb[tid]   = temp_bias[tid * HNUM + h];
    __syncthreads();

    const bool  is_seed = (i < SEEDS);
    const float ti      = time_vec[i];

    float* __restrict__ orow =
        out + ((size_t)h * NTOK + (size_t)i) * (size_t)NTOK;

    // 4096 elements / (256 threads * 4) = 4 float4 iterations per thread
    #pragma unroll
    for (int j0 = tid * 4; j0 < NTOK; j0 += 256 * 4) {
        const int4 t4 = *reinterpret_cast<const int4*>(token_type + j0);
        float4 v;
        v.x = val8[t4.x];
        v.y = val8[t4.y];
        v.z = val8[t4.z];
        v.w = val8[t4.w];
        if (is_seed) {
            const float4 tv = *reinterpret_cast<const float4*>(time_vec + j0);
            v.x += tb[bucketize(tv.x - ti)];
            v.y += tb[bucketize(tv.y - ti)];
            v.z += tb[bucketize(tv.z - ti)];
            v.w += tb[bucketize(tv.w - ti)];
        }
        *reinterpret_cast<float4*>(orow + j0) = v;
    }
}

// ---------------------------------------------------------------------------
// Edge scatter: one thread per (edge, head). 1M independent fp32 atomic adds
// into scattered addresses -> REDG path, ~1 cyc/lane chip-wide.
// ---------------------------------------------------------------------------
__global__ __launch_bounds__(256) void edge_kernel(
    const int*   __restrict__ edge_src,
    const int*   __restrict__ edge_dst,
    const int*   __restrict__ edge_rel,
    const float* __restrict__ adj_rel_bias,   // (R, H)
    float*       __restrict__ out)            // (H, N, N)
{
    const int idx = blockIdx.x * blockDim.x + threadIdx.x;
    if (idx >= NEDGE * HNUM) return;
    const int e = idx >> 3;        // edge index
    const int h = idx & 7;         // head
    const int s = edge_src[e];
    const int d = edge_dst[e];
    const int r = edge_rel[e];
    const float add = adj_rel_bias[r * HNUM + h];
    atomicAdd(out + (size_t)h * NTOK * NTOK + (size_t)s * NTOK + d, add);
}

// ---------------------------------------------------------------------------
// kernel_launch
// Input order (setup_inputs dict): token_type, edge_src, edge_dst, edge_rel,
// time_vec, [seed_count?], adj_rel_bias, typepair_bias, temp_bias.
// seed_count may or may not materialize as a device input; index the trailing
// bias tables from the end to be robust.
// ---------------------------------------------------------------------------
extern "C" void kernel_launch(void* const* d_in, const int* in_sizes, int n_in,
                              void* d_out, int out_size)
{
    const int*   token_type    = (const int*)  d_in[0];
    const int*   edge_src      = (const int*)  d_in[1];
    const int*   edge_dst      = (const int*)  d_in[2];
    const int*   edge_rel      = (const int*)  d_in[3];
    const float* time_vec      = (const float*)d_in[4];
    const float* adj_rel_bias  = (const float*)d_in[n_in - 3];
    const float* typepair_bias = (const float*)d_in[n_in - 2];
    const float* temp_bias     = (const float*)d_in[n_in - 1];
    float* out = (float*)d_out;

    dim3 grid_fill(NTOK, HNUM);
    fill_kernel<<<grid_fill, 256>>>(token_type, time_vec, typepair_bias,
                                    temp_bias, out);

    const int total = NEDGE * HNUM;
    edge_kernel<<<(total + 255) / 256, 256>>>(edge_src, edge_dst, edge_rel,
                                              adj_rel_bias, out);
}